// round 6
// baseline (speedup 1.0000x reference)
#include <cuda_runtime.h>
#include <cuda_bf16.h>

#define BQ 8
#define NQ 900
#define CC 256
#define HEADS 8
#define PP 4
#define HD 32
#define BEVH 200
#define BEVW 200
#define RADIUS 0.2f
#define MROWS 20                 // query rows per CTA; 900 = 45 * 20
#define GROUPS (NQ / MROWS)      // 45
#define RHALF (MROWS / 2)        // 10
#define NT 512

__global__ __launch_bounds__(NT, 3)
void deform_attn_kernel(
    const float* __restrict__ query,
    const float* __restrict__ memory,
    const float* __restrict__ refp,
    const float* __restrict__ w_off,
    const float* __restrict__ b_off,
    const float* __restrict__ w_wt,
    const float* __restrict__ b_wt,
    const float* __restrict__ w_out,
    const float* __restrict__ b_out,
    float* __restrict__ out)
{
    // buf_s: query rows (phases A,B) then fused rows (phases D,E) — disjoint lifetimes.
    __shared__ float buf_s[MROWS][CC];               // 20 KB
    __shared__ float proj_s[MROWS][HEADS * PP * 3];  // [0,64)=off, [64,96)=wt : 7.5 KB
    // aux: phase-B partial scratch (1920 floats), then sx/sy/wts for C/D.
    __shared__ float aux[3 * MROWS * HEADS * PP];    // 7.5 KB
    __shared__ float ref_s[MROWS][2];
#define SXv(r, p) aux[(r) * 32 + (p)]
#define SYv(r, p) aux[640 + (r) * 32 + (p)]
#define WTv(r, p) aux[1280 + (r) * 32 + (p)]

    const int bid = blockIdx.x;
    const int b = bid / GROUPS;
    const int g = bid % GROUPS;
    const int n0 = g * MROWS;
    const int t = threadIdx.x;

    // ---- Phase A: load MROWS query rows (coalesced) + refp stage ----
    {
        const float* qbase = query + ((size_t)b * NQ + n0) * CC;
        #pragma unroll
        for (int i = 0; i < (MROWS * CC) / NT; i++) {
            const int idx = t + i * NT;
            buf_s[idx >> 8][idx & 255] = qbase[idx];
        }
        if (t < MROWS * 2)
            ref_s[t >> 1][t & 1] = refp[((size_t)b * NQ + n0) * 2 + t];
    }
    __syncthreads();

    // ---- Phase B: projections, k-split. 384 active threads =
    //      96 cols x 2 row-halves x 2 k-halves. Weights read 2x per CTA. ----
    if (t < 384) {
        const int col = t % 96;
        const int sub = t / 96;           // 0..3
        const int r0 = (sub & 1) * RHALF;
        const int kh = sub >> 1;
        const float* w;
        int ld;
        float bias;
        if (col < 64) { w = w_off + col; ld = 64; bias = b_off[col]; }
        else          { w = w_wt + (col - 64); ld = 32; bias = b_wt[col - 64]; }

        float acc[RHALF];
        #pragma unroll
        for (int r = 0; r < RHALF; r++) acc[r] = (kh == 0) ? bias : 0.0f;

        const int k0 = kh * (CC / 2);
        for (int k = k0; k < k0 + CC / 2; k += 4) {
            const float w0 = w[(size_t)(k + 0) * ld];
            const float w1 = w[(size_t)(k + 1) * ld];
            const float w2 = w[(size_t)(k + 2) * ld];
            const float w3 = w[(size_t)(k + 3) * ld];
            #pragma unroll
            for (int r = 0; r < RHALF; r++) {
                const float4 q = *reinterpret_cast<const float4*>(&buf_s[r0 + r][k]);
                acc[r] = fmaf(q.x, w0, acc[r]);
                acc[r] = fmaf(q.y, w1, acc[r]);
                acc[r] = fmaf(q.z, w2, acc[r]);
                acc[r] = fmaf(q.w, w3, acc[r]);
            }
        }
        if (kh == 0) {
            #pragma unroll
            for (int r = 0; r < RHALF; r++) proj_s[r0 + r][col] = acc[r];
        } else {
            #pragma unroll
            for (int r = 0; r < RHALF; r++) aux[(r0 + r) * 96 + col] = acc[r];
        }
    }
    __syncthreads();
    // reduce k-halves: proj += aux (1920 elements)
    {
        float* pf = &proj_s[0][0];
        #pragma unroll 4
        for (int i = t; i < MROWS * 96; i += NT) pf[i] += aux[i];
    }
    __syncthreads();

    // ---- Phase C: sampling coords (640 pairs) + per-head softmax (160) ----
    {
        #pragma unroll
        for (int i = 0; i < (MROWS * 32 + NT - 1) / NT; i++) {
            const int o = t + i * NT;
            if (o < MROWS * 32) {
                const int row = o / 32;
                const int pair = o % 32;
                const float rx = ref_s[row][0];
                const float ry = ref_s[row][1];
                const float ox = tanhf(proj_s[row][pair * 2 + 0]) * RADIUS;
                const float oy = tanhf(proj_s[row][pair * 2 + 1]) * RADIUS;
                SXv(row, pair) = (rx + ox) * (float)BEVW - 0.5f;
                SYv(row, pair) = (ry + oy) * (float)BEVH - 0.5f;
            }
        }
        if (t < MROWS * HEADS) {   // 160
            const int row = t >> 3;
            const int h = t & 7;
            const float l0 = proj_s[row][64 + h * 4 + 0];
            const float l1 = proj_s[row][64 + h * 4 + 1];
            const float l2 = proj_s[row][64 + h * 4 + 2];
            const float l3 = proj_s[row][64 + h * 4 + 3];
            const float m = fmaxf(fmaxf(l0, l1), fmaxf(l2, l3));
            const float e0 = __expf(l0 - m);
            const float e1 = __expf(l1 - m);
            const float e2 = __expf(l2 - m);
            const float e3 = __expf(l3 - m);
            const float inv = 1.0f / (e0 + e1 + e2 + e3);
            WTv(row, h * 4 + 0) = e0 * inv;
            WTv(row, h * 4 + 1) = e1 * inv;
            WTv(row, h * 4 + 2) = e2 * inv;
            WTv(row, h * 4 + 3) = e3 * inv;
        }
    }
    __syncthreads();

    // ---- Phase D: bilinear gather, row-split across thread halves.
    //      thread = (rowhalf, head, channel); overwrites buf_s with fused. ----
    {
        const int d = t & 31;            // channel 0..31
        const int h = (t >> 5) & 7;      // head 0..7
        const int r0 = (t >> 8) * RHALF; // 0 or 10
        const float* mb = memory + (size_t)b * (BEVH * BEVW) * CC + h * HD + d;
        #pragma unroll 2
        for (int rr = 0; rr < RHALF; rr++) {
            const int r = r0 + rr;
            float acc = 0.0f;
            #pragma unroll
            for (int p = 0; p < PP; p++) {
                const int pair = h * PP + p;
                const float xx = SXv(r, pair);
                const float yy = SYv(r, pair);
                const float x0f = floorf(xx);
                const float y0f = floorf(yy);
                const float fx = xx - x0f;
                const float fy = yy - y0f;
                const int x0 = (int)x0f;
                const int y0 = (int)y0f;
                const int x1 = x0 + 1;
                const int y1 = y0 + 1;
                const bool vx0 = (x0 >= 0) & (x0 < BEVW);
                const bool vx1 = (x1 >= 0) & (x1 < BEVW);
                const bool vy0 = (y0 >= 0) & (y0 < BEVH);
                const bool vy1 = (y1 >= 0) & (y1 < BEVH);
                const float v00 = (vx0 && vy0) ? mb[(size_t)(y0 * BEVW + x0) * CC] : 0.0f;
                const float v01 = (vx1 && vy0) ? mb[(size_t)(y0 * BEVW + x1) * CC] : 0.0f;
                const float v10 = (vx0 && vy1) ? mb[(size_t)(y1 * BEVW + x0) * CC] : 0.0f;
                const float v11 = (vx1 && vy1) ? mb[(size_t)(y1 * BEVW + x1) * CC] : 0.0f;
                const float top = v00 * (1.0f - fx) + v01 * fx;
                const float bot = v10 * (1.0f - fx) + v11 * fx;
                acc = fmaf(WTv(r, pair), top * (1.0f - fy) + bot * fy, acc);
            }
            buf_s[r][h * HD + d] = acc;
        }
    }
    __syncthreads();

    // ---- Phase E: output projection, row-split. thread = (rowhalf, column) ----
    {
        const int col = t & 255;
        const int r0 = (t >> 8) * RHALF;
        float acc[RHALF];
        const float bo = b_out[col];
        #pragma unroll
        for (int r = 0; r < RHALF; r++) acc[r] = bo;

        const float* w = w_out + col;
        for (int k = 0; k < CC; k += 4) {
            const float w0 = w[(size_t)(k + 0) * CC];
            const float w1 = w[(size_t)(k + 1) * CC];
            const float w2 = w[(size_t)(k + 2) * CC];
            const float w3 = w[(size_t)(k + 3) * CC];
            #pragma unroll
            for (int r = 0; r < RHALF; r++) {
                const float4 f = *reinterpret_cast<const float4*>(&buf_s[r0 + r][k]);
                acc[r] = fmaf(f.x, w0, acc[r]);
                acc[r] = fmaf(f.y, w1, acc[r]);
                acc[r] = fmaf(f.z, w2, acc[r]);
                acc[r] = fmaf(f.w, w3, acc[r]);
            }
        }
        float* obase = out + ((size_t)b * NQ + n0 + r0) * CC + col;
        #pragma unroll
        for (int r = 0; r < RHALF; r++)
            obase[(size_t)r * CC] = acc[r];
    }
#undef SXv
#undef SYv
#undef WTv
}

extern "C" void kernel_launch(void* const* d_in, const int* in_sizes, int n_in,
                              void* d_out, int out_size) {
    const float* query  = (const float*)d_in[0];
    const float* memory = (const float*)d_in[1];
    const float* refp   = (const float*)d_in[2];
    const float* w_off  = (const float*)d_in[3];
    const float* b_off  = (const float*)d_in[4];
    const float* w_wt   = (const float*)d_in[5];
    const float* b_wt   = (const float*)d_in[6];
    const float* w_out  = (const float*)d_in[7];
    const float* b_out  = (const float*)d_in[8];
    // d_in[9], d_in[10] = bev_h, bev_w (200x200, compiled in)

    float* out = (float*)d_out;
    deform_attn_kernel<<<BQ * GROUPS, NT>>>(query, memory, refp, w_off, b_off,
                                            w_wt, b_wt, w_out, b_out, out);
}

// round 8
// speedup vs baseline: 1.0646x; 1.0646x over previous
#include <cuda_runtime.h>
#include <cuda_bf16.h>

#define BQ 8
#define NQ 900
#define CC 256
#define HEADS 8
#define PP 4
#define HD 32
#define BEVH 200
#define BEVW 200
#define RADIUS 0.2f
#define MROWS 20                 // query rows per CTA; 900 = 45 * 20
#define GROUPS (NQ / MROWS)      // 45
#define RHALF (MROWS / 2)        // 10
#define NT 512

typedef unsigned long long ull;

__device__ __forceinline__ void fma2(ull& d, ull a, ull b) {
    asm("fma.rn.f32x2 %0, %1, %2, %0;" : "+l"(d) : "l"(a), "l"(b));
}
__device__ __forceinline__ ull add2(ull a, ull b) {
    ull r; asm("add.rn.f32x2 %0, %1, %2;" : "=l"(r) : "l"(a), "l"(b)); return r;
}
__device__ __forceinline__ ull pack2(float x, float y) {
    ull r; asm("mov.b64 %0, {%1, %2};" : "=l"(r) : "f"(x), "f"(y)); return r;
}
__device__ __forceinline__ float2 unpack2(ull v) {
    float2 r; asm("mov.b64 {%0, %1}, %2;" : "=f"(r.x), "=f"(r.y) : "l"(v)); return r;
}

__global__ __launch_bounds__(NT, 3)
void deform_attn_kernel(
    const float* __restrict__ query,
    const float* __restrict__ memory,
    const float* __restrict__ refp,
    const float* __restrict__ w_off,
    const float* __restrict__ b_off,
    const float* __restrict__ w_wt,
    const float* __restrict__ b_wt,
    const float* __restrict__ w_out,
    const float* __restrict__ b_out,
    float* __restrict__ out)
{
    // buf_s: row-pair interleaved tile: float idx = (rp*CC + k)*2 + (r&1).
    // Holds query (phases A,B) then fused (phases D,E) — disjoint lifetimes.
    __shared__ __align__(16) float buf_s[MROWS * CC];              // 20 KB
    __shared__ __align__(16) float proj_s[MROWS][HEADS * PP * 3];  // 7.5 KB
    __shared__ __align__(16) float aux[3 * MROWS * HEADS * PP];    // 7.5 KB
    __shared__ __align__(8)  float ref_s[MROWS][2];
#define SXv(r, p) aux[(r) * 32 + (p)]
#define SYv(r, p) aux[640 + (r) * 32 + (p)]
#define WTv(r, p) aux[1280 + (r) * 32 + (p)]

    const int bid = blockIdx.x;
    const int b = bid / GROUPS;
    const int g = bid % GROUPS;
    const int n0 = g * MROWS;
    const int t = threadIdx.x;

    // ---- Phase A: load MROWS query rows into interleaved buf_s + refp stage ----
    {
        const float* qbase = query + ((size_t)b * NQ + n0) * CC;
        #pragma unroll
        for (int i = 0; i < (MROWS * CC) / NT; i++) {
            const int idx = t + i * NT;
            const int r = idx >> 8;
            const int k = idx & 255;
            buf_s[((r >> 1) * CC + k) * 2 + (r & 1)] = qbase[idx];
        }
        if (t < MROWS * 2)
            ref_s[t >> 1][t & 1] = refp[((size_t)b * NQ + n0) * 2 + t];
    }
    __syncthreads();

    // ---- Phase B: projections with FFMA2 over row pairs.
    //      384 threads = 96 cols x 2 rowpair-halves x 2 k-halves. ----
    if (t < 384) {
        const int col = t % 96;
        const int sub = t / 96;            // 0..3
        const int rp0 = (sub & 1) * 5;     // rowpairs 0-4 or 5-9
        const int kh = sub >> 1;
        const float* w;
        int ld;
        float bias;
        if (col < 64) { w = w_off + col; ld = 64; bias = b_off[col]; }
        else          { w = w_wt + (col - 64); ld = 32; bias = b_wt[col - 64]; }

        ull acc[5];
        const ull init = (kh == 0) ? pack2(bias, bias) : 0ull;
        #pragma unroll
        for (int rp = 0; rp < 5; rp++) acc[rp] = init;

        const int k0 = kh * (CC / 2);
        for (int k = k0; k < k0 + CC / 2; k += 4) {
            const ull pw0 = pack2(w[(size_t)(k + 0) * ld], w[(size_t)(k + 0) * ld]);
            const ull pw1 = pack2(w[(size_t)(k + 1) * ld], w[(size_t)(k + 1) * ld]);
            const ull pw2 = pack2(w[(size_t)(k + 2) * ld], w[(size_t)(k + 2) * ld]);
            const ull pw3 = pack2(w[(size_t)(k + 3) * ld], w[(size_t)(k + 3) * ld]);
            #pragma unroll
            for (int rp = 0; rp < 5; rp++) {
                const ulonglong2 fa = *reinterpret_cast<const ulonglong2*>(
                    &buf_s[((rp0 + rp) * CC + k) * 2]);
                const ulonglong2 fb = *reinterpret_cast<const ulonglong2*>(
                    &buf_s[((rp0 + rp) * CC + k + 2) * 2]);
                fma2(acc[rp], fa.x, pw0);
                fma2(acc[rp], fa.y, pw1);
                fma2(acc[rp], fb.x, pw2);
                fma2(acc[rp], fb.y, pw3);
            }
        }
        ull* dst = (kh == 0) ? reinterpret_cast<ull*>(&proj_s[0][0])
                             : reinterpret_cast<ull*>(aux);
        #pragma unroll
        for (int rp = 0; rp < 5; rp++)
            dst[(rp0 + rp) * 96 + col] = acc[rp];
    }
    __syncthreads();

    // ---- reduce k-halves and unpack to scalar proj_s layout ----
    {
        const ull* p0 = reinterpret_cast<const ull*>(&proj_s[0][0]);
        const ull* p1 = reinterpret_cast<const ull*>(aux);
        const int i0 = t;
        const int i1 = t + NT;
        float2 v0, v1;
        v0 = unpack2(add2(p0[i0], p1[i0]));                 // i0 < 512 < 960 always
        const bool has1 = (i1 < (MROWS / 2) * 96);          // 960
        if (has1) v1 = unpack2(add2(p0[i1], p1[i1]));
        __syncthreads();
        {
            const int rp = i0 / 96, col = i0 % 96;
            proj_s[2 * rp][col] = v0.x;
            proj_s[2 * rp + 1][col] = v0.y;
        }
        if (has1) {
            const int rp = i1 / 96, col = i1 % 96;
            proj_s[2 * rp][col] = v1.x;
            proj_s[2 * rp + 1][col] = v1.y;
        }
    }
    __syncthreads();

    // ---- Phase C: sampling coords (640 pairs) + per-head softmax (160) ----
    {
        #pragma unroll
        for (int i = 0; i < (MROWS * 32 + NT - 1) / NT; i++) {
            const int o = t + i * NT;
            if (o < MROWS * 32) {
                const int row = o / 32;
                const int pair = o % 32;
                const float rx = ref_s[row][0];
                const float ry = ref_s[row][1];
                const float ox = tanhf(proj_s[row][pair * 2 + 0]) * RADIUS;
                const float oy = tanhf(proj_s[row][pair * 2 + 1]) * RADIUS;
                SXv(row, pair) = (rx + ox) * (float)BEVW - 0.5f;
                SYv(row, pair) = (ry + oy) * (float)BEVH - 0.5f;
            }
        }
        if (t < MROWS * HEADS) {   // 160
            const int row = t >> 3;
            const int h = t & 7;
            const float l0 = proj_s[row][64 + h * 4 + 0];
            const float l1 = proj_s[row][64 + h * 4 + 1];
            const float l2 = proj_s[row][64 + h * 4 + 2];
            const float l3 = proj_s[row][64 + h * 4 + 3];
            const float m = fmaxf(fmaxf(l0, l1), fmaxf(l2, l3));
            const float e0 = __expf(l0 - m);
            const float e1 = __expf(l1 - m);
            const float e2 = __expf(l2 - m);
            const float e3 = __expf(l3 - m);
            const float inv = 1.0f / (e0 + e1 + e2 + e3);
            WTv(row, h * 4 + 0) = e0 * inv;
            WTv(row, h * 4 + 1) = e1 * inv;
            WTv(row, h * 4 + 2) = e2 * inv;
            WTv(row, h * 4 + 3) = e3 * inv;
        }
    }
    __syncthreads();

    // ---- Phase D: bilinear gather, row-split; writes interleaved buf_s ----
    {
        const int d = t & 31;            // channel 0..31
        const int h = (t >> 5) & 7;      // head 0..7
        const int r0 = (t >> 8) * RHALF; // 0 or 10
        const int c = h * HD + d;
        const float* mb = memory + (size_t)b * (BEVH * BEVW) * CC + c;
        #pragma unroll 2
        for (int rr = 0; rr < RHALF; rr++) {
            const int r = r0 + rr;
            float acc = 0.0f;
            #pragma unroll
            for (int p = 0; p < PP; p++) {
                const int pair = h * PP + p;
                const float xx = SXv(r, pair);
                const float yy = SYv(r, pair);
                const float x0f = floorf(xx);
                const float y0f = floorf(yy);
                const float fx = xx - x0f;
                const float fy = yy - y0f;
                const int x0 = (int)x0f;
                const int y0 = (int)y0f;
                const int x1 = x0 + 1;
                const int y1 = y0 + 1;
                const bool vx0 = (x0 >= 0) & (x0 < BEVW);
                const bool vx1 = (x1 >= 0) & (x1 < BEVW);
                const bool vy0 = (y0 >= 0) & (y0 < BEVH);
                const bool vy1 = (y1 >= 0) & (y1 < BEVH);
                const float v00 = (vx0 && vy0) ? mb[(size_t)(y0 * BEVW + x0) * CC] : 0.0f;
                const float v01 = (vx1 && vy0) ? mb[(size_t)(y0 * BEVW + x1) * CC] : 0.0f;
                const float v10 = (vx0 && vy1) ? mb[(size_t)(y1 * BEVW + x0) * CC] : 0.0f;
                const float v11 = (vx1 && vy1) ? mb[(size_t)(y1 * BEVW + x1) * CC] : 0.0f;
                const float top = v00 * (1.0f - fx) + v01 * fx;
                const float bot = v10 * (1.0f - fx) + v11 * fx;
                acc = fmaf(WTv(r, pair), top * (1.0f - fy) + bot * fy, acc);
            }
            buf_s[((r >> 1) * CC + c) * 2 + (r & 1)] = acc;
        }
    }
    __syncthreads();

    // ---- Phase E: output projection with FFMA2 over row pairs.
    //      thread = (rowpair-half, column). ----
    {
        const int col = t & 255;
        const int rp0 = (t >> 8) * 5;    // rowpairs 0-4 or 5-9
        const float bo = b_out[col];
        ull acc[5];
        const ull binit = pack2(bo, bo);
        #pragma unroll
        for (int rp = 0; rp < 5; rp++) acc[rp] = binit;

        const float* w = w_out + col;
        for (int k = 0; k < CC; k += 4) {
            const ull pw0 = pack2(w[(size_t)(k + 0) * CC], w[(size_t)(k + 0) * CC]);
            const ull pw1 = pack2(w[(size_t)(k + 1) * CC], w[(size_t)(k + 1) * CC]);
            const ull pw2 = pack2(w[(size_t)(k + 2) * CC], w[(size_t)(k + 2) * CC]);
            const ull pw3 = pack2(w[(size_t)(k + 3) * CC], w[(size_t)(k + 3) * CC]);
            #pragma unroll
            for (int rp = 0; rp < 5; rp++) {
                const ulonglong2 fa = *reinterpret_cast<const ulonglong2*>(
                    &buf_s[((rp0 + rp) * CC + k) * 2]);
                const ulonglong2 fb = *reinterpret_cast<const ulonglong2*>(
                    &buf_s[((rp0 + rp) * CC + k + 2) * 2]);
                fma2(acc[rp], fa.x, pw0);
                fma2(acc[rp], fa.y, pw1);
                fma2(acc[rp], fb.x, pw2);
                fma2(acc[rp], fb.y, pw3);
            }
        }
        float* obase = out + ((size_t)b * NQ + n0) * CC + col;
        #pragma unroll
        for (int rp = 0; rp < 5; rp++) {
            const float2 v = unpack2(acc[rp]);
            const int r = (rp0 + rp) * 2;
            obase[(size_t)r * CC] = v.x;
            obase[(size_t)(r + 1) * CC] = v.y;
        }
    }
#undef SXv
#undef SYv
#undef WTv
}

extern "C" void kernel_launch(void* const* d_in, const int* in_sizes, int n_in,
                              void* d_out, int out_size) {
    const float* query  = (const float*)d_in[0];
    const float* memory = (const float*)d_in[1];
    const float* refp   = (const float*)d_in[2];
    const float* w_off  = (const float*)d_in[3];
    const float* b_off  = (const float*)d_in[4];
    const float* w_wt   = (const float*)d_in[5];
    const float* b_wt   = (const float*)d_in[6];
    const float* w_out  = (const float*)d_in[7];
    const float* b_out  = (const float*)d_in[8];
    // d_in[9], d_in[10] = bev_h, bev_w (200x200, compiled in)

    float* out = (float*)d_out;
    deform_attn_kernel<<<BQ * GROUPS, NT>>>(query, memory, refp, w_off, b_off,
                                            w_wt, b_wt, w_out, b_out, out);
}

// round 9
// speedup vs baseline: 1.4193x; 1.3332x over previous
#include <cuda_runtime.h>
#include <cuda_bf16.h>

#define BQ 8
#define NQ 900
#define CC 256
#define HEADS 8
#define PP 4
#define HD 32
#define BEVH 200
#define BEVW 200
#define RADIUS 0.2f
#define MROWS 25                 // query rows per CTA; 900 = 36 * 25
#define GROUPS (NQ / MROWS)      // 36 -> grid 288 = 2 CTAs/SM balanced
#define NPAIR 12                 // rows 0..23 as 12 interleaved pairs; row 24 scalar
#define NT 512

typedef unsigned long long ull;

__device__ __forceinline__ void fma2(ull& d, ull a, ull b) {
    asm("fma.rn.f32x2 %0, %1, %2, %0;" : "+l"(d) : "l"(a), "l"(b));
}
__device__ __forceinline__ ull pack2(float x, float y) {
    ull r; asm("mov.b64 %0, {%1, %2};" : "=l"(r) : "f"(x), "f"(y)); return r;
}
__device__ __forceinline__ float2 unpack2(ull v) {
    float2 r; asm("mov.b64 {%0, %1}, %2;" : "=f"(r.x), "=f"(r.y) : "l"(v)); return r;
}

__global__ __launch_bounds__(NT, 2)
void deform_attn_kernel(
    const float* __restrict__ query,
    const float* __restrict__ memory,
    const float* __restrict__ refp,
    const float* __restrict__ w_off,
    const float* __restrict__ b_off,
    const float* __restrict__ w_wt,
    const float* __restrict__ b_wt,
    const float* __restrict__ w_out,
    const float* __restrict__ b_out,
    float* __restrict__ out)
{
    // buf_s: rows 0..23 pair-interleaved (float idx = (rp*CC+k)*2 + (r&1));
    //        row 24 scalar at offset 24*CC. Query (A,B) then fused (D,E).
    __shared__ __align__(16) float buf_s[MROWS * CC];        // 25 KB
    __shared__ __align__(16) float proj_s[MROWS][96];        // 9.375 KB
    __shared__ __align__(16) float aux[MROWS * 96];          // 9.375 KB (B partials, then sx/sy/wt)
    __shared__ __align__(8)  float ref_s[MROWS][2];
#define SXv(r, p) aux[(r) * 32 + (p)]
#define SYv(r, p) aux[800 + (r) * 32 + (p)]
#define WTv(r, p) aux[1600 + (r) * 32 + (p)]

    const int bid = blockIdx.x;
    const int b = bid / GROUPS;
    const int g = bid % GROUPS;
    const int n0 = g * MROWS;
    const int t = threadIdx.x;

    // ---- Phase A: load 25 query rows (interleaved pairs + scalar row 24) ----
    {
        const float* qbase = query + ((size_t)b * NQ + n0) * CC;
        #pragma unroll
        for (int i = 0; i < (MROWS * CC + NT - 1) / NT; i++) {
            const int idx = t + i * NT;
            if (idx < MROWS * CC) {
                const int r = idx >> 8;
                const int k = idx & 255;
                const int dst = (r < 24) ? (((r >> 1) * CC + k) * 2 + (r & 1))
                                         : (24 * CC + k);
                buf_s[dst] = qbase[idx];
            }
        }
        if (t < MROWS * 2)
            ref_s[t >> 1][t & 1] = refp[((size_t)b * NQ + n0) * 2 + t];
    }
    __syncthreads();

    // ---- Phase B: projections, FFMA2 row-pairs + scalar row 24, k-split x2.
    //      384 threads = 96 cols x 2 rowhalves x 2 khalves. ----
    if (t < 384) {
        const int col = t % 96;
        const int sub = t / 96;           // 0..3
        const int rh = sub & 1;           // rowpairs 0-5 or 6-11 (+row24)
        const int kh = sub >> 1;
        const int rp0 = rh * 6;
        const float* w;
        int ld;
        float bias;
        if (col < 64) { w = w_off + col; ld = 64; bias = b_off[col]; }
        else          { w = w_wt + (col - 64); ld = 32; bias = b_wt[col - 64]; }

        ull acc[6];
        const ull init = (kh == 0) ? pack2(bias, bias) : 0ull;
        #pragma unroll
        for (int rp = 0; rp < 6; rp++) acc[rp] = init;
        float acc24 = (rh == 1 && kh == 0) ? bias : 0.0f;

        const int k0 = kh * (CC / 2);
        for (int k = k0; k < k0 + CC / 2; k += 4) {
            const float w0 = w[(size_t)(k + 0) * ld];
            const float w1 = w[(size_t)(k + 1) * ld];
            const float w2 = w[(size_t)(k + 2) * ld];
            const float w3 = w[(size_t)(k + 3) * ld];
            const ull pw0 = pack2(w0, w0);
            const ull pw1 = pack2(w1, w1);
            const ull pw2 = pack2(w2, w2);
            const ull pw3 = pack2(w3, w3);
            #pragma unroll
            for (int rp = 0; rp < 6; rp++) {
                const ulonglong2 fa = *reinterpret_cast<const ulonglong2*>(
                    &buf_s[((rp0 + rp) * CC + k) * 2]);
                const ulonglong2 fb = *reinterpret_cast<const ulonglong2*>(
                    &buf_s[((rp0 + rp) * CC + k + 2) * 2]);
                fma2(acc[rp], fa.x, pw0);
                fma2(acc[rp], fa.y, pw1);
                fma2(acc[rp], fb.x, pw2);
                fma2(acc[rp], fb.y, pw3);
            }
            if (rh == 1) {
                const float4 q = *reinterpret_cast<const float4*>(&buf_s[24 * CC + k]);
                acc24 = fmaf(q.x, w0, acc24);
                acc24 = fmaf(q.y, w1, acc24);
                acc24 = fmaf(q.z, w2, acc24);
                acc24 = fmaf(q.w, w3, acc24);
            }
        }
        if (kh == 0) {
            #pragma unroll
            for (int rp = 0; rp < 6; rp++) {
                const float2 v = unpack2(acc[rp]);
                proj_s[(rp0 + rp) * 2][col] = v.x;
                proj_s[(rp0 + rp) * 2 + 1][col] = v.y;
            }
            if (rh == 1) proj_s[24][col] = acc24;
        } else {
            #pragma unroll
            for (int rp = 0; rp < 6; rp++) {
                const float2 v = unpack2(acc[rp]);
                aux[((rp0 + rp) * 2) * 96 + col] = v.x;
                aux[((rp0 + rp) * 2 + 1) * 96 + col] = v.y;
            }
            if (rh == 1) aux[24 * 96 + col] = acc24;
        }
    }
    __syncthreads();
    // reduce k-halves: proj += aux (2400 elements)
    {
        float* pf = &proj_s[0][0];
        #pragma unroll
        for (int i = t; i < MROWS * 96; i += NT) pf[i] += aux[i];
    }
    __syncthreads();

    // ---- Phase C: sampling coords (800 pairs) + per-head softmax (200) ----
    {
        #pragma unroll
        for (int i = 0; i < (MROWS * 32 + NT - 1) / NT; i++) {
            const int o = t + i * NT;
            if (o < MROWS * 32) {
                const int row = o / 32;
                const int pair = o % 32;
                const float rx = ref_s[row][0];
                const float ry = ref_s[row][1];
                const float ox = tanhf(proj_s[row][pair * 2 + 0]) * RADIUS;
                const float oy = tanhf(proj_s[row][pair * 2 + 1]) * RADIUS;
                SXv(row, pair) = (rx + ox) * (float)BEVW - 0.5f;
                SYv(row, pair) = (ry + oy) * (float)BEVH - 0.5f;
            }
        }
        if (t < MROWS * HEADS) {   // 200
            const int row = t >> 3;
            const int h = t & 7;
            const float l0 = proj_s[row][64 + h * 4 + 0];
            const float l1 = proj_s[row][64 + h * 4 + 1];
            const float l2 = proj_s[row][64 + h * 4 + 2];
            const float l3 = proj_s[row][64 + h * 4 + 3];
            const float m = fmaxf(fmaxf(l0, l1), fmaxf(l2, l3));
            const float e0 = __expf(l0 - m);
            const float e1 = __expf(l1 - m);
            const float e2 = __expf(l2 - m);
            const float e3 = __expf(l3 - m);
            const float inv = 1.0f / (e0 + e1 + e2 + e3);
            WTv(row, h * 4 + 0) = e0 * inv;
            WTv(row, h * 4 + 1) = e1 * inv;
            WTv(row, h * 4 + 2) = e2 * inv;
            WTv(row, h * 4 + 3) = e3 * inv;
        }
    }
    __syncthreads();

    // ---- Phase D: bilinear gather, 13/12 row split across thread halves ----
    {
        const int d = t & 31;            // channel 0..31
        const int h = (t >> 5) & 7;      // head 0..7
        const int hh = t >> 8;           // 0 or 1
        const int r0 = hh ? 13 : 0;
        const int cnt = hh ? 12 : 13;
        const int c = h * HD + d;
        const float* mb = memory + (size_t)b * (BEVH * BEVW) * CC + c;
        for (int rr = 0; rr < cnt; rr++) {
            const int r = r0 + rr;
            float acc = 0.0f;
            #pragma unroll
            for (int p = 0; p < PP; p++) {
                const int pair = h * PP + p;
                const float xx = SXv(r, pair);
                const float yy = SYv(r, pair);
                const float x0f = floorf(xx);
                const float y0f = floorf(yy);
                const float fx = xx - x0f;
                const float fy = yy - y0f;
                const int x0 = (int)x0f;
                const int y0 = (int)y0f;
                const int x1 = x0 + 1;
                const int y1 = y0 + 1;
                const bool vx0 = (x0 >= 0) & (x0 < BEVW);
                const bool vx1 = (x1 >= 0) & (x1 < BEVW);
                const bool vy0 = (y0 >= 0) & (y0 < BEVH);
                const bool vy1 = (y1 >= 0) & (y1 < BEVH);
                const float v00 = (vx0 && vy0) ? mb[(size_t)(y0 * BEVW + x0) * CC] : 0.0f;
                const float v01 = (vx1 && vy0) ? mb[(size_t)(y0 * BEVW + x1) * CC] : 0.0f;
                const float v10 = (vx0 && vy1) ? mb[(size_t)(y1 * BEVW + x0) * CC] : 0.0f;
                const float v11 = (vx1 && vy1) ? mb[(size_t)(y1 * BEVW + x1) * CC] : 0.0f;
                const float top = v00 * (1.0f - fx) + v01 * fx;
                const float bot = v10 * (1.0f - fx) + v11 * fx;
                acc = fmaf(WTv(r, pair), top * (1.0f - fy) + bot * fy, acc);
            }
            const int dst = (r < 24) ? (((r >> 1) * CC + c) * 2 + (r & 1))
                                     : (24 * CC + c);
            buf_s[dst] = acc;
        }
    }
    __syncthreads();

    // ---- Phase E: output projection, FFMA2 row-pairs. thread = (rowhalf, col).
    //      half0: rowpairs 0-5 (rows 0-11); half1: rowpairs 6-11 + row 24. ----
    {
        const int col = t & 255;
        const int hh = t >> 8;
        const int rp0 = hh * 6;
        const float bo = b_out[col];
        ull acc[6];
        const ull binit = pack2(bo, bo);
        #pragma unroll
        for (int rp = 0; rp < 6; rp++) acc[rp] = binit;
        float acc24 = bo;

        const float* w = w_out + col;
        for (int k = 0; k < CC; k += 4) {
            const float w0 = w[(size_t)(k + 0) * CC];
            const float w1 = w[(size_t)(k + 1) * CC];
            const float w2 = w[(size_t)(k + 2) * CC];
            const float w3 = w[(size_t)(k + 3) * CC];
            const ull pw0 = pack2(w0, w0);
            const ull pw1 = pack2(w1, w1);
            const ull pw2 = pack2(w2, w2);
            const ull pw3 = pack2(w3, w3);
            #pragma unroll
            for (int rp = 0; rp < 6; rp++) {
                const ulonglong2 fa = *reinterpret_cast<const ulonglong2*>(
                    &buf_s[((rp0 + rp) * CC + k) * 2]);
                const ulonglong2 fb = *reinterpret_cast<const ulonglong2*>(
                    &buf_s[((rp0 + rp) * CC + k + 2) * 2]);
                fma2(acc[rp], fa.x, pw0);
                fma2(acc[rp], fa.y, pw1);
                fma2(acc[rp], fb.x, pw2);
                fma2(acc[rp], fb.y, pw3);
            }
            if (hh) {
                const float4 f = *reinterpret_cast<const float4*>(&buf_s[24 * CC + k]);
                acc24 = fmaf(f.x, w0, acc24);
                acc24 = fmaf(f.y, w1, acc24);
                acc24 = fmaf(f.z, w2, acc24);
                acc24 = fmaf(f.w, w3, acc24);
            }
        }
        float* obase = out + ((size_t)b * NQ + n0) * CC + col;
        #pragma unroll
        for (int rp = 0; rp < 6; rp++) {
            const float2 v = unpack2(acc[rp]);
            const int r = (rp0 + rp) * 2;
            obase[(size_t)r * CC] = v.x;
            obase[(size_t)(r + 1) * CC] = v.y;
        }
        if (hh) obase[(size_t)24 * CC] = acc24;
    }
#undef SXv
#undef SYv
#undef WTv
}

extern "C" void kernel_launch(void* const* d_in, const int* in_sizes, int n_in,
                              void* d_out, int out_size) {
    const float* query  = (const float*)d_in[0];
    const float* memory = (const float*)d_in[1];
    const float* refp   = (const float*)d_in[2];
    const float* w_off  = (const float*)d_in[3];
    const float* b_off  = (const float*)d_in[4];
    const float* w_wt   = (const float*)d_in[5];
    const float* b_wt   = (const float*)d_in[6];
    const float* w_out  = (const float*)d_in[7];
    const float* b_out  = (const float*)d_in[8];
    // d_in[9], d_in[10] = bev_h, bev_w (200x200, compiled in)

    float* out = (float*)d_out;
    deform_attn_kernel<<<BQ * GROUPS, NT>>>(query, memory, refp, w_off, b_off,
                                            w_wt, b_wt, w_out, b_out, out);
}

// round 12
// speedup vs baseline: 1.5116x; 1.0650x over previous
#include <cuda_runtime.h>
#include <cuda_bf16.h>

#define BQ 8
#define NQ 900
#define CC 256
#define HEADS 8
#define PP 4
#define HD 32
#define BEVH 200
#define BEVW 200
#define RADIUS 0.2f
#define MROWS 25                 // query rows per CTA; 900 = 36 * 25
#define GROUPS (NQ / MROWS)      // 36 -> grid 288 ~= 2 CTAs/SM balanced
#define NT 512

typedef unsigned long long ull;

__device__ __forceinline__ void fma2(ull& d, ull a, ull b) {
    asm("fma.rn.f32x2 %0, %1, %2, %0;" : "+l"(d) : "l"(a), "l"(b));
}
__device__ __forceinline__ ull pack2(float x, float y) {
    ull r; asm("mov.b64 %0, {%1, %2};" : "=l"(r) : "f"(x), "f"(y)); return r;
}
__device__ __forceinline__ float2 unpack2(ull v) {
    float2 r; asm("mov.b64 {%0, %1}, %2;" : "=f"(r.x), "=f"(r.y) : "l"(v)); return r;
}

__global__ __launch_bounds__(NT, 2)
void deform_attn_kernel(
    const float* __restrict__ query,
    const float* __restrict__ memory,
    const float* __restrict__ refp,
    const float* __restrict__ w_off,
    const float* __restrict__ b_off,
    const float* __restrict__ w_wt,
    const float* __restrict__ b_wt,
    const float* __restrict__ w_out,
    const float* __restrict__ b_out,
    float* __restrict__ out)
{
    // buf_s: rows 0..23 pair-interleaved (float idx = (rp*CC+k)*2 + (r&1));
    //        row 24 scalar at offset 24*CC. Query (A,B) then fused (D,E).
    __shared__ __align__(16) float buf_s[MROWS * CC];        // 25 KB
    __shared__ __align__(16) float proj_s[MROWS][96];        // 9.375 KB
    __shared__ __align__(16) float aux[MROWS * 96];          // 9.375 KB (B partials, then sx/sy/wt)
    __shared__ __align__(8)  float ref_s[MROWS][2];
#define SXv(r, p) aux[(r) * 32 + (p)]
#define SYv(r, p) aux[800 + (r) * 32 + (p)]
#define WTv(r, p) aux[1600 + (r) * 32 + (p)]

    const int bid = blockIdx.x;
    const int b = bid / GROUPS;
    const int g = bid % GROUPS;
    const int n0 = g * MROWS;
    const int t = threadIdx.x;

    // ---- Phase A: load 25 query rows (interleaved pairs + scalar row 24) ----
    {
        const float* qbase = query + ((size_t)b * NQ + n0) * CC;
        #pragma unroll
        for (int i = 0; i < (MROWS * CC + NT - 1) / NT; i++) {
            const int idx = t + i * NT;
            if (idx < MROWS * CC) {
                const int r = idx >> 8;
                const int k = idx & 255;
                const int dst = (r < 24) ? (((r >> 1) * CC + k) * 2 + (r & 1))
                                         : (24 * CC + k);
                buf_s[dst] = qbase[idx];
            }
        }
        if (t < MROWS * 2)
            ref_s[t >> 1][t & 1] = refp[((size_t)b * NQ + n0) * 2 + t];
    }
    __syncthreads();

    // ---- Phase B: projections, FFMA2 row-pairs + scalar row 24, k-split x2.
    //      384 threads = 96 cols x 2 rowhalves x 2 khalves. ----
    if (t < 384) {
        const int col = t % 96;
        const int sub = t / 96;           // 0..3
        const int rh = sub & 1;           // rowpairs 0-5 or 6-11 (+row24)
        const int kh = sub >> 1;
        const int rp0 = rh * 6;
        const float* w;
        int ld;
        float bias;
        if (col < 64) { w = w_off + col; ld = 64; bias = b_off[col]; }
        else          { w = w_wt + (col - 64); ld = 32; bias = b_wt[col - 64]; }

        ull acc[6];
        const ull init = (kh == 0) ? pack2(bias, bias) : 0ull;
        #pragma unroll
        for (int rp = 0; rp < 6; rp++) acc[rp] = init;
        float acc24 = (rh == 1 && kh == 0) ? bias : 0.0f;

        const int k0 = kh * (CC / 2);
        for (int k = k0; k < k0 + CC / 2; k += 4) {
            const float w0 = w[(size_t)(k + 0) * ld];
            const float w1 = w[(size_t)(k + 1) * ld];
            const float w2 = w[(size_t)(k + 2) * ld];
            const float w3 = w[(size_t)(k + 3) * ld];
            const ull pw0 = pack2(w0, w0);
            const ull pw1 = pack2(w1, w1);
            const ull pw2 = pack2(w2, w2);
            const ull pw3 = pack2(w3, w3);
            #pragma unroll
            for (int rp = 0; rp < 6; rp++) {
                const ulonglong2 fa = *reinterpret_cast<const ulonglong2*>(
                    &buf_s[((rp0 + rp) * CC + k) * 2]);
                const ulonglong2 fb = *reinterpret_cast<const ulonglong2*>(
                    &buf_s[((rp0 + rp) * CC + k + 2) * 2]);
                fma2(acc[rp], fa.x, pw0);
                fma2(acc[rp], fa.y, pw1);
                fma2(acc[rp], fb.x, pw2);
                fma2(acc[rp], fb.y, pw3);
            }
            if (rh == 1) {
                const float4 q = *reinterpret_cast<const float4*>(&buf_s[24 * CC + k]);
                acc24 = fmaf(q.x, w0, acc24);
                acc24 = fmaf(q.y, w1, acc24);
                acc24 = fmaf(q.z, w2, acc24);
                acc24 = fmaf(q.w, w3, acc24);
            }
        }
        if (kh == 0) {
            #pragma unroll
            for (int rp = 0; rp < 6; rp++) {
                const float2 v = unpack2(acc[rp]);
                proj_s[(rp0 + rp) * 2][col] = v.x;
                proj_s[(rp0 + rp) * 2 + 1][col] = v.y;
            }
            if (rh == 1) proj_s[24][col] = acc24;
        } else {
            #pragma unroll
            for (int rp = 0; rp < 6; rp++) {
                const float2 v = unpack2(acc[rp]);
                aux[((rp0 + rp) * 2) * 96 + col] = v.x;
                aux[((rp0 + rp) * 2 + 1) * 96 + col] = v.y;
            }
            if (rh == 1) aux[24 * 96 + col] = acc24;
        }
    }
    __syncthreads();
    // reduce k-halves: proj += aux (2400 elements)
    {
        float* pf = &proj_s[0][0];
        #pragma unroll
        for (int i = t; i < MROWS * 96; i += NT) pf[i] += aux[i];
    }
    __syncthreads();

    // ---- Phase C: sampling coords (800 pairs) + per-head softmax (200) ----
    {
        #pragma unroll
        for (int i = 0; i < (MROWS * 32 + NT - 1) / NT; i++) {
            const int o = t + i * NT;
            if (o < MROWS * 32) {
                const int row = o / 32;
                const int pair = o % 32;
                const float rx = ref_s[row][0];
                const float ry = ref_s[row][1];
                const float ox = tanhf(proj_s[row][pair * 2 + 0]) * RADIUS;
                const float oy = tanhf(proj_s[row][pair * 2 + 1]) * RADIUS;
                SXv(row, pair) = (rx + ox) * (float)BEVW - 0.5f;
                SYv(row, pair) = (ry + oy) * (float)BEVH - 0.5f;
            }
        }
        if (t < MROWS * HEADS) {   // 200
            const int row = t >> 3;
            const int h = t & 7;
            const float l0 = proj_s[row][64 + h * 4 + 0];
            const float l1 = proj_s[row][64 + h * 4 + 1];
            const float l2 = proj_s[row][64 + h * 4 + 2];
            const float l3 = proj_s[row][64 + h * 4 + 3];
            const float m = fmaxf(fmaxf(l0, l1), fmaxf(l2, l3));
            const float e0 = __expf(l0 - m);
            const float e1 = __expf(l1 - m);
            const float e2 = __expf(l2 - m);
            const float e3 = __expf(l3 - m);
            const float inv = 1.0f / (e0 + e1 + e2 + e3);
            WTv(row, h * 4 + 0) = e0 * inv;
            WTv(row, h * 4 + 1) = e1 * inv;
            WTv(row, h * 4 + 2) = e2 * inv;
            WTv(row, h * 4 + 3) = e3 * inv;
        }
    }
    __syncthreads();

    // ---- Phase D: bilinear gather, float4-vectorized, CLAMPED addresses.
    //      All loads are unconditional at in-bounds addresses; validity is
    //      folded into the bilinear weights (no predicated wide loads).
    //      Rows 0..23: thread = (rowslot 8, head 8, quad 8); 3 rows/thread.
    //      Row 24: scalar path on threads 0..255 (head, channel). ----
    {
        const int q4 = t & 7;            // channel quad 0..7
        const int h = (t >> 3) & 7;      // head 0..7
        const int rslot = t >> 6;        // 0..7
        const int c = h * HD + q4 * 4;
        const float* mb = memory + (size_t)b * (BEVH * BEVW) * CC + c;
        #pragma unroll
        for (int i = 0; i < 3; i++) {
            const int r = rslot + i * 8;   // 0..23
            float4 acc = make_float4(0.f, 0.f, 0.f, 0.f);
            #pragma unroll
            for (int p = 0; p < PP; p++) {
                const int pair = h * PP + p;
                const float xx = SXv(r, pair);
                const float yy = SYv(r, pair);
                const float x0f = floorf(xx);
                const float y0f = floorf(yy);
                const float fx = xx - x0f;
                const float fy = yy - y0f;
                const int x0 = (int)x0f;
                const int y0 = (int)y0f;
                const int x1 = x0 + 1;
                const int y1 = y0 + 1;
                // validity folded into weights
                const float wx0 = (1.0f - fx) * (float)((x0 >= 0) & (x0 < BEVW));
                const float wx1 = fx * (float)((x1 >= 0) & (x1 < BEVW));
                const float wyt = (1.0f - fy) * (float)((y0 >= 0) & (y0 < BEVH));
                const float wyb = fy * (float)((y1 >= 0) & (y1 < BEVH));
                // clamped, always-valid addresses
                const int x0c = min(max(x0, 0), BEVW - 1);
                const int x1c = min(max(x1, 0), BEVW - 1);
                const int y0c = min(max(y0, 0), BEVH - 1);
                const int y1c = min(max(y1, 0), BEVH - 1);
                const float4 v00 = *reinterpret_cast<const float4*>(mb + (size_t)(y0c * BEVW + x0c) * CC);
                const float4 v01 = *reinterpret_cast<const float4*>(mb + (size_t)(y0c * BEVW + x1c) * CC);
                const float4 v10 = *reinterpret_cast<const float4*>(mb + (size_t)(y1c * BEVW + x0c) * CC);
                const float4 v11 = *reinterpret_cast<const float4*>(mb + (size_t)(y1c * BEVW + x1c) * CC);
                const float wt = WTv(r, pair);
                acc.x = fmaf(wt, (v00.x * wx0 + v01.x * wx1) * wyt + (v10.x * wx0 + v11.x * wx1) * wyb, acc.x);
                acc.y = fmaf(wt, (v00.y * wx0 + v01.y * wx1) * wyt + (v10.y * wx0 + v11.y * wx1) * wyb, acc.y);
                acc.z = fmaf(wt, (v00.z * wx0 + v01.z * wx1) * wyt + (v10.z * wx0 + v11.z * wx1) * wyb, acc.z);
                acc.w = fmaf(wt, (v00.w * wx0 + v01.w * wx1) * wyt + (v10.w * wx0 + v11.w * wx1) * wyb, acc.w);
            }
            // store: rows <24 are pair-interleaved, stride 2 floats per channel
            const int base = ((r >> 1) * CC + c) * 2 + (r & 1);
            buf_s[base + 0] = acc.x;
            buf_s[base + 2] = acc.y;
            buf_s[base + 4] = acc.z;
            buf_s[base + 6] = acc.w;
        }
        // row 24 scalar path (same clamped-unconditional scheme)
        if (t < 256) {
            const int hs = t >> 5;
            const int ds = t & 31;
            const int cs = hs * HD + ds;
            const float* mbs = memory + (size_t)b * (BEVH * BEVW) * CC + cs;
            float acc = 0.0f;
            #pragma unroll
            for (int p = 0; p < PP; p++) {
                const int pair = hs * PP + p;
                const float xx = SXv(24, pair);
                const float yy = SYv(24, pair);
                const float x0f = floorf(xx);
                const float y0f = floorf(yy);
                const float fx = xx - x0f;
                const float fy = yy - y0f;
                const int x0 = (int)x0f;
                const int y0 = (int)y0f;
                const int x1 = x0 + 1;
                const int y1 = y0 + 1;
                const float wx0 = (1.0f - fx) * (float)((x0 >= 0) & (x0 < BEVW));
                const float wx1 = fx * (float)((x1 >= 0) & (x1 < BEVW));
                const float wyt = (1.0f - fy) * (float)((y0 >= 0) & (y0 < BEVH));
                const float wyb = fy * (float)((y1 >= 0) & (y1 < BEVH));
                const int x0c = min(max(x0, 0), BEVW - 1);
                const int x1c = min(max(x1, 0), BEVW - 1);
                const int y0c = min(max(y0, 0), BEVH - 1);
                const int y1c = min(max(y1, 0), BEVH - 1);
                const float v00 = mbs[(size_t)(y0c * BEVW + x0c) * CC];
                const float v01 = mbs[(size_t)(y0c * BEVW + x1c) * CC];
                const float v10 = mbs[(size_t)(y1c * BEVW + x0c) * CC];
                const float v11 = mbs[(size_t)(y1c * BEVW + x1c) * CC];
                acc = fmaf(WTv(24, pair),
                           (v00 * wx0 + v01 * wx1) * wyt + (v10 * wx0 + v11 * wx1) * wyb,
                           acc);
            }
            buf_s[24 * CC + cs] = acc;
        }
    }
    __syncthreads();

    // ---- Phase E: output projection, FFMA2 row-pairs. thread = (rowhalf, col).
    //      half0: rowpairs 0-5 (rows 0-11); half1: rowpairs 6-11 + row 24. ----
    {
        const int col = t & 255;
        const int hh = t >> 8;
        const int rp0 = hh * 6;
        const float bo = b_out[col];
        ull acc[6];
        const ull binit = pack2(bo, bo);
        #pragma unroll
        for (int rp = 0; rp < 6; rp++) acc[rp] = binit;
        float acc24 = bo;

        const float* w = w_out + col;
        for (int k = 0; k < CC; k += 4) {
            const float w0 = w[(size_t)(k + 0) * CC];
            const float w1 = w[(size_t)(k + 1) * CC];
            const float w2 = w[(size_t)(k + 2) * CC];
            const float w3 = w[(size_t)(k + 3) * CC];
            const ull pw0 = pack2(w0, w0);
            const ull pw1 = pack2(w1, w1);
            const ull pw2 = pack2(w2, w2);
            const ull pw3 = pack2(w3, w3);
            #pragma unroll
            for (int rp = 0; rp < 6; rp++) {
                const ulonglong2 fa = *reinterpret_cast<const ulonglong2*>(
                    &buf_s[((rp0 + rp) * CC + k) * 2]);
                const ulonglong2 fb = *reinterpret_cast<const ulonglong2*>(
                    &buf_s[((rp0 + rp) * CC + k + 2) * 2]);
                fma2(acc[rp], fa.x, pw0);
                fma2(acc[rp], fa.y, pw1);
                fma2(acc[rp], fb.x, pw2);
                fma2(acc[rp], fb.y, pw3);
            }
            if (hh) {
                const float4 f = *reinterpret_cast<const float4*>(&buf_s[24 * CC + k]);
                acc24 = fmaf(f.x, w0, acc24);
                acc24 = fmaf(f.y, w1, acc24);
                acc24 = fmaf(f.z, w2, acc24);
                acc24 = fmaf(f.w, w3, acc24);
            }
        }
        float* obase = out + ((size_t)b * NQ + n0) * CC + col;
        #pragma unroll
        for (int rp = 0; rp < 6; rp++) {
            const float2 v = unpack2(acc[rp]);
            const int r = (rp0 + rp) * 2;
            obase[(size_t)r * CC] = v.x;
            obase[(size_t)(r + 1) * CC] = v.y;
        }
        if (hh) obase[(size_t)24 * CC] = acc24;
    }
#undef SXv
#undef SYv
#undef WTv
}

extern "C" void kernel_launch(void* const* d_in, const int* in_sizes, int n_in,
                              void* d_out, int out_size) {
    const float* query  = (const float*)d_in[0];
    const float* memory = (const float*)d_in[1];
    const float* refp   = (const float*)d_in[2];
    const float* w_off  = (const float*)d_in[3];
    const float* b_off  = (const float*)d_in[4];
    const float* w_wt   = (const float*)d_in[5];
    const float* b_wt   = (const float*)d_in[6];
    const float* w_out  = (const float*)d_in[7];
    const float* b_out  = (const float*)d_in[8];
    // d_in[9], d_in[10] = bev_h, bev_w (200x200, compiled in)

    float* out = (float*)d_out;
    deform_attn_kernel<<<BQ * GROUPS, NT>>>(query, memory, refp, w_off, b_off,
                                            w_wt, b_wt, w_out, b_out, out);
}